// round 15
// baseline (speedup 1.0000x reference)
#include <cuda_runtime.h>
#include <cuda_bf16.h>
#include <cstdint>

#define BATCH 8
#define SEQ 512
#define DM 512
#define NELEM (BATCH*SEQ*DM)

// ============================ scratch (bf16 hi/lo splits, pass-1 only) ============================
__device__ __align__(16) __nv_bfloat16 g_QRhi[NELEM];
__device__ __align__(16) __nv_bfloat16 g_QRlo[NELEM];
__device__ __align__(16) __nv_bfloat16 g_Ethi[DM*DM];
__device__ __align__(16) __nv_bfloat16 g_Etlo[DM*DM];

__device__ __forceinline__ void split_bf16(float x, __nv_bfloat16& h, __nv_bfloat16& l) {
    h = __float2bfloat16(x);
    l = __float2bfloat16(x - __bfloat162float(h));
}

__device__ __forceinline__ uint32_t smem_u32(const void* p) {
    uint32_t a;
    asm("{ .reg .u64 t; cvta.to.shared.u64 t, %1; cvt.u32.u64 %0, t; }" : "=r"(a) : "l"(p));
    return a;
}

// ============================ prep kernel (QR gather + E transpose only) ============================
#define QBLOCKS (BATCH*SEQ)
#define EBLOCKS 256

__global__ void prep_all_kernel(const float* __restrict__ q,
                                const float* __restrict__ e) {
    __shared__ float sh[32 * 33 + 128];
    int bid = blockIdx.x;
    int t = threadIdx.x;                  // 128 threads

    if (bid < QBLOCKS) {
        float* row = sh;
        float* red = sh + 512;
        int i = bid & (SEQ - 1);
        const float4* src = reinterpret_cast<const float4*>(q + (size_t)bid * DM);
        reinterpret_cast<float4*>(row)[t] = src[t];
        __syncthreads();

        float p = 0.f;
        #pragma unroll
        for (int j = t; j < DM; j += 128)
            if (j >= i) p += row[j];
        red[t] = p;
        __syncthreads();
        #pragma unroll
        for (int s = 64; s > 0; s >>= 1) {
            if (t < s) red[t] += red[t + s];
            __syncthreads();
        }
        float suf = red[0];

        size_t base = (size_t)bid * DM;
        #pragma unroll
        for (int d = t; d < DM; d += 128) {
            float r = (d == 0) ? suf : ((d <= i) ? row[i - d] : 0.f);
            split_bf16(r, g_QRhi[base + d], g_QRlo[base + d]);
        }
    } else {
        float (*tile)[33] = reinterpret_cast<float(*)[33]>(sh);
        int eb = bid - QBLOCKS;
        int bx = eb & 15, by = eb >> 4;
        int tx = t & 31, j0 = t >> 5;
        #pragma unroll
        for (int j = j0; j < 32; j += 4)
            tile[j][tx] = e[(size_t)(by * 32 + j) * DM + bx * 32 + tx];
        __syncthreads();
        #pragma unroll
        for (int j = j0; j < 32; j += 4) {
            size_t o = (size_t)(bx * 32 + j) * DM + by * 32 + tx;
            split_bf16(tile[tx][j], g_Ethi[o], g_Etlo[o]);
        }
    }
}

// ============================ main GEMM: warp-specialized + pipelined consumer ============================
// 128x128 CTA tile. 384 threads: warps 0-7 consumers (4x2, warp tile 32x64),
// warps 8-11 producers. Pass 0: producers LDG fp32 Q/K (batched MLP), split, STS.
// Pass 1: producers cp.async bf16 QR/Et tiles. 3-stage mbarrier pipeline.
// Consumer pipelines at half-k16 granularity: LDSM(u+1) before MMA(u).
// Pass 1 skips all-zero K-chunks: tile at m0=128*by needs 2*by+2 of 8.

#define BM 128
#define BN 128
#define BK 64
#define THREADS 384
#define NCONS 256
#define TILE_HB (BM * BK * 2)                // 16384 per hi/lo tile
#define STAGE_B (4 * TILE_HB)                // 65536: Ahi,Alo,Bhi,Blo
#define NSTAGE 3
#define MBAR_OFF (NSTAGE * STAGE_B)
#define SMEM_TOTAL (MBAR_OFF + 64)

#define OFF_AH 0
#define OFF_AL TILE_HB
#define OFF_BH (2 * TILE_HB)
#define OFF_BL (3 * TILE_HB)

__device__ __forceinline__ uint32_t sw_off(int row, int kk) {
    return (uint32_t)(row * 128 + (((kk >> 3) ^ (row & 7)) << 4) + ((kk & 7) << 1));
}

__device__ __forceinline__ void cp_async16(uint32_t saddr, const void* gaddr) {
    asm volatile("cp.async.cg.shared.global [%0], [%1], 16;" :: "r"(saddr), "l"(gaddr));
}

__device__ __forceinline__ void sts128(uint32_t saddr, uint4 v) {
    asm volatile("st.shared.v4.b32 [%0], {%1,%2,%3,%4};"
                 :: "r"(saddr), "r"(v.x), "r"(v.y), "r"(v.z), "r"(v.w) : "memory");
}

#define MBARRIER_INIT(addr, count) \
    asm volatile("mbarrier.init.shared.b64 [%0], %1;" :: "r"((uint32_t)(addr)), "r"((uint32_t)(count)) : "memory")

#define MBARRIER_ARRIVE(addr) \
    asm volatile("mbarrier.arrive.shared.b64 _, [%0];" :: "r"((uint32_t)(addr)) : "memory")

#define CPASYNC_MBARRIER_ARRIVE_NOINC(addr) \
    asm volatile("cp.async.mbarrier.arrive.noinc.shared.b64 [%0];" :: "r"((uint32_t)(addr)) : "memory")

#define MBARRIER_WAIT_PARITY(addr, parity) do { \
    uint32_t _m = (uint32_t)(addr), _p = (uint32_t)(parity), _d; \
    asm volatile( \
        "{\n\t.reg .pred p;\n\t" \
        "mbarrier.try_wait.parity.acquire.cta.shared::cta.b64 p, [%1], %2;\n\t" \
        "selp.b32 %0, 1, 0, p;\n\t}" \
        : "=r"(_d) : "r"(_m), "r"(_p) : "memory"); \
    if (!_d) { \
        asm volatile( \
            "{\n\t.reg .pred P1;\n\t" \
            "WL_%=:\n\t" \
            "mbarrier.try_wait.parity.acquire.cta.shared::cta.b64 P1, [%0], %1;\n\t" \
            "@P1 bra.uni WD_%=;\n\t" \
            "bra.uni WL_%=;\n\t" \
            "WD_%=:\n\t}" \
            :: "r"(_m), "r"(_p) : "memory"); \
    } \
} while(0)

__device__ __forceinline__ void ldmatrix_x4(uint32_t& r0, uint32_t& r1, uint32_t& r2,
                                            uint32_t& r3, uint32_t addr) {
    asm volatile("ldmatrix.sync.aligned.m8n8.x4.shared.b16 {%0,%1,%2,%3}, [%4];"
                 : "=r"(r0), "=r"(r1), "=r"(r2), "=r"(r3) : "r"(addr));
}

__device__ __forceinline__ void mma16816(float* c, const uint32_t* a, uint32_t b0, uint32_t b1) {
    asm volatile(
        "mma.sync.aligned.m16n8k16.row.col.f32.bf16.bf16.f32 "
        "{%0,%1,%2,%3}, {%4,%5,%6,%7}, {%8,%9}, {%0,%1,%2,%3};"
        : "+f"(c[0]), "+f"(c[1]), "+f"(c[2]), "+f"(c[3])
        : "r"(a[0]), "r"(a[1]), "r"(a[2]), "r"(a[3]), "r"(b0), "r"(b1));
}

// split 8 consecutive fp32 (2 float4) into 16B hi + 16B lo packs
__device__ __forceinline__ void split8(float4 v0, float4 v1, uint4& H, uint4& L) {
    __nv_bfloat16 h[8], l[8];
    split_bf16(v0.x, h[0], l[0]); split_bf16(v0.y, h[1], l[1]);
    split_bf16(v0.z, h[2], l[2]); split_bf16(v0.w, h[3], l[3]);
    split_bf16(v1.x, h[4], l[4]); split_bf16(v1.y, h[5], l[5]);
    split_bf16(v1.z, h[6], l[6]); split_bf16(v1.w, h[7], l[7]);
    H = *reinterpret_cast<uint4*>(h);
    L = *reinterpret_cast<uint4*>(l);
}

__global__ __launch_bounds__(THREADS, 1) void rel_gemm_kernel(
        float* __restrict__ out,
        const float* __restrict__ qf,
        const float* __restrict__ kf) {
    extern __shared__ char smem[];
    uint32_t sb = smem_u32(smem);
    uint32_t mb_full  = sb + MBAR_OFF;
    uint32_t mb_empty = sb + MBAR_OFF + 24;

    int tid = threadIdx.x;
    int lane = tid & 31, wid = tid >> 5;
    int n0 = blockIdx.x * BN;
    int m0 = blockIdx.y * BM;
    int b  = blockIdx.z;
    size_t boff = (size_t)b * SEQ * DM;
    int total = 10 + 2 * (int)blockIdx.y;     // pass0: 8 chunks, pass1: 2*by+2

    if (tid == 0) {
        #pragma unroll
        for (int s = 0; s < NSTAGE; s++) {
            MBARRIER_INIT(mb_full + s * 8, 128);
            MBARRIER_INIT(mb_empty + s * 8, NCONS);
        }
    }
    __syncthreads();

    if (wid >= 8) {
        // ================= producers (warps 8-11, 128 threads) =================
        int ptid = tid - NCONS;               // 0..127
        const float* qbase = qf + boff + (size_t)m0 * DM;
        const float* kbase = kf + boff + (size_t)n0 * DM;
        const __nv_bfloat16* qr_h = g_QRhi + boff + (size_t)m0 * DM;
        const __nv_bfloat16* qr_l = g_QRlo + boff + (size_t)m0 * DM;
        const __nv_bfloat16* et_h = g_Ethi + (size_t)n0 * DM;
        const __nv_bfloat16* et_l = g_Etlo + (size_t)n0 * DM;

        for (int c = 0; c < total; c++) {
            int s = c % NSTAGE, f = c / NSTAGE;
            if (f >= 1) MBARRIER_WAIT_PARITY(mb_empty + s * 8, (f - 1) & 1);
            uint32_t st = sb + s * STAGE_B;
            int kc = c & 7;

            if (c < 8) {
                // pass 0: batched LDG fp32 (MLP=16), split, STS
                #pragma unroll
                for (int bb = 0; bb < 2; bb++) {
                    float4 qv[4][2], kv[4][2];
                    #pragma unroll
                    for (int r = 0; r < 4; r++) {
                        int idx = ptid + (bb * 4 + r) * 128;
                        int row = idx >> 3, ck = idx & 7;
                        const float4* qa = reinterpret_cast<const float4*>(
                            qbase + (size_t)row * DM + kc * BK + ck * 8);
                        const float4* ka = reinterpret_cast<const float4*>(
                            kbase + (size_t)row * DM + kc * BK + ck * 8);
                        qv[r][0] = qa[0]; qv[r][1] = qa[1];
                        kv[r][0] = ka[0]; kv[r][1] = ka[1];
                    }
                    #pragma unroll
                    for (int r = 0; r < 4; r++) {
                        int idx = ptid + (bb * 4 + r) * 128;
                        int row = idx >> 3, ck = idx & 7;
                        uint32_t so = (uint32_t)(row * 128 + ((ck ^ (row & 7)) << 4));
                        uint4 H, L;
                        split8(qv[r][0], qv[r][1], H, L);
                        sts128(st + OFF_AH + so, H);
                        sts128(st + OFF_AL + so, L);
                        split8(kv[r][0], kv[r][1], H, L);
                        sts128(st + OFF_BH + so, H);
                        sts128(st + OFF_BL + so, L);
                    }
                }
                MBARRIER_ARRIVE(mb_full + s * 8);   // release: STS visible to acquirers
            } else {
                // pass 1: cp.async bf16 QR / Et tiles
                const __nv_bfloat16* pah = qr_h + kc * BK;
                const __nv_bfloat16* pal = qr_l + kc * BK;
                const __nv_bfloat16* pbh = et_h + kc * BK;
                const __nv_bfloat16* pbl = et_l + kc * BK;
                #pragma unroll
                for (int r2 = 0; r2 < 8; r2++) {
                    int idx = ptid + r2 * 128;
                    int row = idx >> 3, ck = idx & 7;
                    uint32_t so = (uint32_t)(row * 128 + ((ck ^ (row & 7)) << 4));
                    cp_async16(st + OFF_AH + so, pah + row * DM + ck * 8);
                    cp_async16(st + OFF_AL + so, pal + row * DM + ck * 8);
                    cp_async16(st + OFF_BH + so, pbh + row * DM + ck * 8);
                    cp_async16(st + OFF_BL + so, pbl + row * DM + ck * 8);
                }
                CPASYNC_MBARRIER_ARRIVE_NOINC(mb_full + s * 8);
            }
        }
        return;
    }

    // ================= consumers (warps 0-7, warp tile 32x64) =================
    int wm = wid & 3, wn = wid >> 2;
    int a_row = wm * 32 + (lane & 7) + ((lane >> 3) & 1) * 8;   // + mi*16
    int a_kk  = (lane >> 4) << 3;                               // + kc
    int b_row = wn * 64 + (lane & 7) + ((lane >> 4) << 3);      // + nb*16
    int b_kk  = ((lane >> 3) & 1) << 3;                         // + kc

    float acc[2][8][4];
    #pragma unroll
    for (int mi = 0; mi < 2; mi++)
        #pragma unroll
        for (int ni = 0; ni < 8; ni++)
            #pragma unroll
            for (int j = 0; j < 4; j++) acc[mi][ni][j] = 0.f;

    // pipelined fragment buffers: A per-k16 (2 bufs), B per half-k16 (2 bufs)
    uint32_t ah[2][2][4], al[2][2][4];   // [k16 parity][mi][4]
    uint32_t bh[2][2][4], bl[2][2][4];   // [unit parity][nbin][4]

    for (int c = 0; c < total; c++) {
        int s = c % NSTAGE, f = c / NSTAGE;
        MBARRIER_WAIT_PARITY(mb_full + s * 8, f & 1);
        uint32_t st = sb + s * STAGE_B;

        // load unit 0: A(k16=0) -> buf0, B(k16=0, h=0) -> buf0
        #pragma unroll
        for (int mi = 0; mi < 2; mi++) {
            uint32_t so = sw_off(a_row + mi * 16, a_kk);
            ldmatrix_x4(ah[0][mi][0], ah[0][mi][1], ah[0][mi][2], ah[0][mi][3], st + OFF_AH + so);
            ldmatrix_x4(al[0][mi][0], al[0][mi][1], al[0][mi][2], al[0][mi][3], st + OFF_AL + so);
        }
        #pragma unroll
        for (int nbin = 0; nbin < 2; nbin++) {
            uint32_t so = sw_off(b_row + nbin * 16, b_kk);
            ldmatrix_x4(bh[0][nbin][0], bh[0][nbin][1], bh[0][nbin][2], bh[0][nbin][3], st + OFF_BH + so);
            ldmatrix_x4(bl[0][nbin][0], bl[0][nbin][1], bl[0][nbin][2], bl[0][nbin][3], st + OFF_BL + so);
        }

        // 8 units: u = k16*2 + h. Prefetch LDSM(u+1), then MMA(u).
        #pragma unroll
        for (int u = 0; u < 8; u++) {
            int k16 = u >> 1, h = u & 1;
            if (u < 7) {
                int nu = u + 1, nk = nu >> 1, nh = nu & 1;
                int nkc = nk * 16;
                if (nh == 0) {
                    int pa = nk & 1;
                    #pragma unroll
                    for (int mi = 0; mi < 2; mi++) {
                        uint32_t so = sw_off(a_row + mi * 16, a_kk + nkc);
                        ldmatrix_x4(ah[pa][mi][0], ah[pa][mi][1], ah[pa][mi][2], ah[pa][mi][3],
                                    st + OFF_AH + so);
                        ldmatrix_x4(al[pa][mi][0], al[pa][mi][1], al[pa][mi][2], al[pa][mi][3],
                                    st + OFF_AL + so);
                    }
                }
                int pb = nu & 1;
                #pragma unroll
                for (int nbin = 0; nbin < 2; nbin++) {
                    uint32_t so = sw_off(b_row + (nh * 2 + nbin) * 16, b_kk + nkc);
                    ldmatrix_x4(bh[pb][nbin][0], bh[pb][nbin][1], bh[pb][nbin][2], bh[pb][nbin][3],
                                st + OFF_BH + so);
                    ldmatrix_x4(bl[pb][nbin][0], bl[pb][nbin][1], bl[pb][nbin][2], bl[pb][nbin][3],
                                st + OFF_BL + so);
                }
            }
            // MMA(u): 24 MMAs, term-grouped
            int pa = k16 & 1, pb = u & 1;
            #pragma unroll
            for (int mi = 0; mi < 2; mi++)            // hi*hi
                #pragma unroll
                for (int nbin = 0; nbin < 2; nbin++)
                    #pragma unroll
                    for (int n8 = 0; n8 < 2; n8++)
                        mma16816(acc[mi][(h * 2 + nbin) * 2 + n8], ah[pa][mi],
                                 bh[pb][nbin][2 * n8], bh[pb][nbin][2 * n8 + 1]);
            #pragma unroll
            for (int mi = 0; mi < 2; mi++)            // hi*lo
                #pragma unroll
                for (int nbin = 0; nbin < 2; nbin++)
                    #pragma unroll
                    for (int n8 = 0; n8 < 2; n8++)
                        mma16816(acc[mi][(h * 2 + nbin) * 2 + n8], ah[pa][mi],
                                 bl[pb][nbin][2 * n8], bl[pb][nbin][2 * n8 + 1]);
            #pragma unroll
            for (int mi = 0; mi < 2; mi++)            // lo*hi
                #pragma unroll
                for (int nbin = 0; nbin < 2; nbin++)
                    #pragma unroll
                    for (int n8 = 0; n8 < 2; n8++)
                        mma16816(acc[mi][(h * 2 + nbin) * 2 + n8], al[pa][mi],
                                 bh[pb][nbin][2 * n8], bh[pb][nbin][2 * n8 + 1]);
        }
        MBARRIER_ARRIVE(mb_empty + s * 8);
    }

    // epilogue (consumers only)
    int qr = lane >> 2, qc = (lane & 3) << 1;
    #pragma unroll
    for (int mi = 0; mi < 2; mi++) {
        int r0 = m0 + wm * 32 + mi * 16 + qr;
        #pragma unroll
        for (int ni = 0; ni < 8; ni++) {
            int cidx = n0 + wn * 64 + ni * 8 + qc;
            float* o0 = out + ((size_t)b * SEQ + r0) * DM + cidx;
            float* o1 = o0 + 8 * DM;
            *reinterpret_cast<float2*>(o0) = make_float2(acc[mi][ni][0], acc[mi][ni][1]);
            *reinterpret_cast<float2*>(o1) = make_float2(acc[mi][ni][2], acc[mi][ni][3]);
        }
    }
}

// ============================ launch ============================
extern "C" void kernel_launch(void* const* d_in, const int* in_sizes, int n_in,
                              void* d_out, int out_size) {
    const float* q = (const float*)d_in[0];
    const float* k = (const float*)d_in[1];
    const float* e = (const float*)d_in[2];
    float* out = (float*)d_out;

    cudaFuncSetAttribute(rel_gemm_kernel,
                         cudaFuncAttributeMaxDynamicSharedMemorySize, SMEM_TOTAL);

    prep_all_kernel<<<QBLOCKS + EBLOCKS, 128>>>(q, e);
    rel_gemm_kernel<<<dim3(SEQ / BN, SEQ / BM, BATCH), THREADS, SMEM_TOTAL>>>(out, q, k);
}